// round 15
// baseline (speedup 1.0000x reference)
#include <cuda_runtime.h>
#include <stdint.h>

#define NB 2
#define NP 8192
#define KS 120
#define KN 30
#define WST 33   // w1s/w2s row stride: odd => conflict-free column access

struct KIdx { int v[KS]; };

// ----------------- device scratch -----------------
__device__ __align__(16) float g_WT[131 * 128];       // transposed conv_w: [c][o]
__device__ __align__(16) float g_gnT[NB][128 * KS];   // [b][c*120+j]
__device__ __align__(16) float g_S[NB][KS * 128];     // [b][j*128+o]
__device__ float  g_Srow[NB][2][KS];
__device__ float  g_SSv [NB][2][KS];
__device__ float  g_SDv [NB][2][KS][3];
__device__ float  g_Dg[2][3];
__device__ float  g_M [2][6];
__device__ double g_stats[NB][2][2];
__device__ __align__(8) float2 g_AJ[(size_t)NB * NP * KN];   // (attn, bitcast j)

__device__ __forceinline__ float wsum(float x) {
#pragma unroll
    for (int d = 16; d; d >>= 1) x += __shfl_xor_sync(0xffffffffu, x, d);
    return x;
}
__device__ __forceinline__ float wmax(float x) {
#pragma unroll
    for (int d = 16; d; d >>= 1) x = fmaxf(x, __shfl_xor_sync(0xffffffffu, x, d));
    return x;
}
__device__ __forceinline__ unsigned ord32(float d) {
    unsigned u = __float_as_uint(d);
    return (u & 0x80000000u) ? ~u : (u | 0x80000000u);
}

#define ICNT(acc, e, k) \
    asm("{.reg .pred p; setp.gt.u32 p, %1, %2; @p add.s32 %0, %0, 1;}" \
        : "+r"(acc) : "r"(e), "r"(k))

template<int N> __device__ __forceinline__ void cpa_wait() {
    asm volatile("cp.async.wait_group %0;" :: "n"(N) : "memory");
}
__device__ __forceinline__ void cpa_commit() {
    asm volatile("cp.async.commit_group;" ::: "memory");
}
__device__ __forceinline__ void cpa8(uint32_t dst, const void* src) {
    asm volatile("cp.async.ca.shared.global [%0], [%1], 8;" :: "r"(dst), "l"(src) : "memory");
}

// ----------------- K_TR: transpose conv_w + aux constants -----------------
__global__ void k_tr(const float* __restrict__ conv_w)
{
    if (blockIdx.y == 4) {
        if (blockIdx.x != 0) return;
        int t = threadIdx.y * 32 + threadIdx.x;
        if (t < 6) {
            int g = t / 3, c = t % 3;
            float a = 0.f;
            for (int o = g * 64; o < g * 64 + 64; o++) a += __ldg(&conv_w[o * 131 + 128 + c]);
            g_Dg[g][c] = a;
        }
        if (t >= 32 && t < 44) {
            int u = t - 32, g = u / 6, e = u % 6;
            const int ti[6] = {0,0,0,1,1,2}, tj2[6] = {0,1,2,1,2,2};
            float a = 0.f;
            for (int o = g * 64; o < g * 64 + 64; o++)
                a += __ldg(&conv_w[o * 131 + 128 + ti[e]]) * __ldg(&conv_w[o * 131 + 128 + tj2[e]]);
            g_M[g][e] = a;
        }
        if (t == 64) { double* z = &g_stats[0][0][0]; for (int x = 0; x < 8; x++) z[x] = 0.0; }
        return;
    }
    __shared__ float tile[32][33];
    int c = blockIdx.x * 32 + threadIdx.x;
    int o = blockIdx.y * 32 + threadIdx.y;
    if (c < 131) tile[threadIdx.y][threadIdx.x] = conv_w[o * 131 + c];
    __syncthreads();
    int c2 = blockIdx.x * 32 + threadIdx.y;
    int o2 = blockIdx.y * 32 + threadIdx.x;
    if (c2 < 131) g_WT[c2 * 128 + o2] = tile[threadIdx.x][threadIdx.y];
}

// ----------------- K0 -----------------
__global__ void k0_prep(const float* __restrict__ points,
                        const float* __restrict__ feature,
                        const float* __restrict__ inst, KIdx kid)
{
    int b = blockIdx.y, j = blockIdx.x, tid = threadIdx.x;
    __shared__ float frow[131];
    __shared__ float red[5][128];
    __shared__ float rsum[4];

    int src = kid.v[j];
    size_t rb = (size_t)b * NP + src;
    float v = inst[rb * 128 + tid];
    frow[tid] = feature[rb * 128 + tid];
    if (tid < 3) frow[128 + tid] = points[rb * 3 + tid];

    float sq = v * v;
#pragma unroll
    for (int d = 16; d; d >>= 1) sq += __shfl_xor_sync(0xffffffffu, sq, d);
    if ((tid & 31) == 0) rsum[tid >> 5] = sq;
    __syncthreads();
    float rn = 1.0f / sqrtf(rsum[0] + rsum[1] + rsum[2] + rsum[3]);
    g_gnT[b][tid * KS + j] = v * rn;

    float s = 0.f;
#pragma unroll 16
    for (int c = 0; c < 131; c++) s = fmaf(g_WT[c * 128 + tid], frow[c], s);
    g_S[b][j * 128 + tid] = s;

    float d0 = g_WT[128 * 128 + tid], d1 = g_WT[129 * 128 + tid], d2 = g_WT[130 * 128 + tid];
    red[0][tid] = s;      red[1][tid] = s * s;
    red[2][tid] = s * d0; red[3][tid] = s * d1; red[4][tid] = s * d2;
    __syncthreads();

    if (tid < 10) {
        int q = tid >> 1, g = tid & 1;
        float a = 0.f;
        for (int t = 0; t < 64; t++) a += red[q][g * 64 + t];
        if (q == 0)      g_Srow[b][g][j] = a;
        else if (q == 1) g_SSv[b][g][j]  = a;
        else             g_SDv[b][g][j][q - 2] = a;
    }
}

// ----------------- K1: threshold-select top-30 (2-point paired search) ----
#define O_GNT   0
#define O_W1    61440
#define O_W2    65400
#define O_SROW  69360
#define O_SSV   70320
#define O_SDV   71280
#define O_FNB   74160
#define O_SELK  90544
#define O_SELV  92464
#define O_SELJ  93424
#define O_TOPD  94384
#define O_TOPJ  95344
#define O_AB    96304
#define O_BACC  97328
#define S1_TOTAL 97360

__global__ void __launch_bounds__(256, 2)
k1_attn(const float* __restrict__ points,
        const float* __restrict__ inst,
        const float* __restrict__ w1g,
        const float* __restrict__ w2g)
{
    extern __shared__ unsigned char sm[];
    float* gnT = (float*)(sm + O_GNT);
    float* w1s = (float*)(sm + O_W1);
    float* w2s = (float*)(sm + O_W2);
    float* srow = (float*)(sm + O_SROW);
    float* ssv  = (float*)(sm + O_SSV);
    float* sdv  = (float*)(sm + O_SDV);
    float* fnb  = (float*)(sm + O_FNB);
    unsigned long long* selkB = (unsigned long long*)(sm + O_SELK);
    float* selvB = (float*)(sm + O_SELV);
    int*   seljB = (int*)(sm + O_SELJ);
    float* topd = (float*)(sm + O_TOPD);
    int*   topj = (int*)(sm + O_TOPJ);
    float* ab   = (float*)(sm + O_AB);
    double* bacc = (double*)(sm + O_BACC);

    int tid = threadIdx.x, b = blockIdx.y;
    {
        float4* dst = (float4*)gnT;
        const float4* srcp = (const float4*)&g_gnT[b][0];
        for (int i = tid; i < 3840; i += 256) dst[i] = srcp[i];
        for (int i = tid; i < 30 * WST; i += 256) {
            int r = i / WST, c = i % WST;
            w1s[i] = (c < 30) ? w1g[r * 30 + c] : 0.f;
            w2s[i] = (c < 30) ? w2g[r * 30 + c] : 0.f;
        }
        const float* a0 = &g_Srow[b][0][0]; const float* a1 = &g_SSv[b][0][0];
        for (int i = tid; i < 240; i += 256) { srow[i] = a0[i]; ssv[i] = a1[i]; }
        const float* a2 = &g_SDv[b][0][0][0];
        for (int i = tid; i < 720; i += 256) sdv[i] = a2[i];
        if (tid < 4) bacc[tid] = 0.0;
    }
    __syncthreads();

    int w = tid >> 5, lane = tid & 31;
    int jl = lane < 30 ? lane : 29;
    int n0 = (blockIdx.x * 8 + w) * 4;
    unsigned long long* selkW = selkB + w * KN;
    float* selvW = selvB + w * KN;
    int*   seljW = seljB + w * KN;
    float* td = topd + w * KN;
    int*   tj = topj + w * KN;
    float* abw = ab + w * 32;
    float* fw = fnb + w * 4 * 128;

    float pxv[4], pyv[4], pzv[4];
#pragma unroll
    for (int p = 0; p < 4; p++) {
        pxv[p] = __ldg(&points[((size_t)b * NP + n0 + p) * 3 + 0]);
        pyv[p] = __ldg(&points[((size_t)b * NP + n0 + p) * 3 + 1]);
        pzv[p] = __ldg(&points[((size_t)b * NP + n0 + p) * 3 + 2]);
    }

    const float4* ip = (const float4*)inst;
#pragma unroll
    for (int p = 0; p < 4; p++) {
        float4 v = ip[((size_t)b * NP + n0 + p) * 32 + lane];
        float rn = 1.0f / sqrtf(wsum(v.x*v.x + v.y*v.y + v.z*v.z + v.w*v.w));
        ((float4*)(fw + p * 128))[lane] = make_float4(v.x*rn, v.y*rn, v.z*rn, v.w*rn);
    }
    __syncwarp();

    // dots (arithmetic order identical to passing kernel)
    float av[4][4];
#pragma unroll
    for (int p = 0; p < 4; p++)
#pragma unroll
        for (int q = 0; q < 4; q++) av[p][q] = 0.f;

    const float4* gnT4 = (const float4*)gnT;
    const float4* f4p[4] = { (const float4*)(fw), (const float4*)(fw + 128),
                             (const float4*)(fw + 256), (const float4*)(fw + 384) };
#pragma unroll 4
    for (int c4 = 0; c4 < 32; c4++) {
        float4 a[4];
#pragma unroll
        for (int p = 0; p < 4; p++) a[p] = f4p[p][c4];
#pragma unroll
        for (int r = 0; r < 4; r++) {
            float4 gv = gnT4[(c4 * 4 + r) * 30 + jl];
#pragma unroll
            for (int p = 0; p < 4; p++) {
                float s = (r == 0) ? a[p].x : (r == 1) ? a[p].y : (r == 2) ? a[p].z : a[p].w;
                av[p][0] = fmaf(s, gv.x, av[p][0]);
                av[p][1] = fmaf(s, gv.y, av[p][1]);
                av[p][2] = fmaf(s, gv.z, av[p][2]);
                av[p][3] = fmaf(s, gv.w, av[p][3]);
            }
        }
    }

    float dg00 = g_Dg[0][0], dg01 = g_Dg[0][1], dg02 = g_Dg[0][2];
    float dg10 = g_Dg[1][0], dg11 = g_Dg[1][1], dg12 = g_Dg[1][2];
    float m0[6], m1[6];
#pragma unroll
    for (int e = 0; e < 6; e++) { m0[e] = g_M[0][e]; m1[e] = g_M[1][e]; }

    double acc0 = 0, acc1 = 0, acc2 = 0, acc3 = 0;

#pragma unroll
    for (int pr = 0; pr < 2; pr++) {
        // --- paired key computation for points 2*pr, 2*pr+1 ---
        unsigned vk[2][4];
#pragma unroll
        for (int pp = 0; pp < 2; pp++)
#pragma unroll
            for (int q = 0; q < 4; q++) {
                av[2*pr + pp][q] -= 1.0f;
                vk[pp][q] = (lane < 30) ? ord32(av[2*pr + pp][q]) : 0u;
            }

        // --- interleaved binary search: 2 independent REDUX chains ---
        unsigned Tp[2] = {0u, 0u};
#pragma unroll
        for (int bit = 31; bit >= 0; bit--) {
#pragma unroll
            for (int pp = 0; pp < 2; pp++) {
                unsigned cand = Tp[pp] | (1u << bit);
                unsigned cm1 = cand - 1u;
                int c = 0;
                ICNT(c, vk[pp][0], cm1); ICNT(c, vk[pp][1], cm1);
                ICNT(c, vk[pp][2], cm1); ICNT(c, vk[pp][3], cm1);
                c = __reduce_add_sync(0xffffffffu, c);
                if (c >= KN) Tp[pp] = cand;
            }
        }

        // --- per-point epilogue (identical to R14) ---
#pragma unroll
        for (int pp = 0; pp < 2; pp++) {
            int p = 2*pr + pp;
            int n = n0 + p;
            float dd0 = av[p][0], dd1 = av[p][1], dd2 = av[p][2], dd3 = av[p][3];
            unsigned v0 = vk[pp][0], v1 = vk[pp][1], v2 = vk[pp][2], v3 = vk[pp][3];
            unsigned T = Tp[pp];

            bool gt0 = v0 > T, gt1 = v1 > T, gt2 = v2 > T, gt3 = v3 > T;
            bool eq0 = v0 == T, eq1 = v1 == T, eq2 = v2 == T, eq3 = v3 == T;
            int G = __reduce_add_sync(0xffffffffu,
                                      (int)gt0 + (int)gt1 + (int)gt2 + (int)gt3);
            int Bq = KN - G;

            unsigned e0 = __ballot_sync(0xffffffffu, eq0);
            unsigned e1 = __ballot_sync(0xffffffffu, eq1);
            unsigned e2 = __ballot_sync(0xffffffffu, eq2);
            unsigned e3 = __ballot_sync(0xffffffffu, eq3);
            unsigned lt = (1u << lane) - 1u;
            int el0 = __popc(e0 & lt) + __popc(e1 & lt) + __popc(e2 & lt) + __popc(e3 & lt);
            int el1 = el0 + (int)eq0;
            int el2 = el1 + (int)eq1;
            int el3 = el2 + (int)eq2;
            bool sel0 = gt0 || (eq0 && el0 < Bq);
            bool sel1 = gt1 || (eq1 && el1 < Bq);
            bool sel2 = gt2 || (eq2 && el2 < Bq);
            bool sel3 = gt3 || (eq3 && el3 < Bq);

            unsigned s0 = __ballot_sync(0xffffffffu, sel0);
            unsigned s1 = __ballot_sync(0xffffffffu, sel1);
            unsigned s2 = __ballot_sync(0xffffffffu, sel2);
            unsigned s3 = __ballot_sync(0xffffffffu, sel3);
            int q0 = __popc(s0 & lt) + __popc(s1 & lt) + __popc(s2 & lt) + __popc(s3 & lt);
            int q1 = q0 + (int)sel0;
            int q2 = q1 + (int)sel1;
            int q3 = q2 + (int)sel2;
            int jb = 4 * lane;
            if (sel0) { selkW[q0] = ((unsigned long long)v0 << 32) | (unsigned)(KS-1-jb);
                        selvW[q0] = dd0; seljW[q0] = jb; }
            if (sel1) { selkW[q1] = ((unsigned long long)v1 << 32) | (unsigned)(KS-2-jb);
                        selvW[q1] = dd1; seljW[q1] = jb + 1; }
            if (sel2) { selkW[q2] = ((unsigned long long)v2 << 32) | (unsigned)(KS-3-jb);
                        selvW[q2] = dd2; seljW[q2] = jb + 2; }
            if (sel3) { selkW[q3] = ((unsigned long long)v3 << 32) | (unsigned)(KS-4-jb);
                        selvW[q3] = dd3; seljW[q3] = jb + 3; }
            __syncwarp();

            if (lane < 30) {
                unsigned long long mykey = selkW[lane];
                int rank = 0;
#pragma unroll 6
                for (int k = 0; k < KN; k++) rank += (int)(selkW[k] > mykey);
                td[rank] = selvW[lane];
                tj[rank] = seljW[lane];
            }
            __syncwarp();

            // kpam layer 1 + relu (stride-33 rows: conflict-free)
            float a1v = 0.f;
            {
                const float* wr = w1s + jl * WST;
                for (int k = 0; k < KN; k++) a1v = fmaf(td[k], wr[k], a1v);
                a1v = fmaxf(a1v, 0.f);
            }
            abw[lane] = a1v;
            __syncwarp();
            float pv = 0.f;
            {
                const float* wr = w2s + jl * WST;
                for (int o = 0; o < KN; o++) pv = fmaf(abw[o], wr[o], pv);
            }
            float pm = (lane < 30) ? pv : -1e30f;
            float mx = wmax(pm);
            float e = (lane < 30) ? __expf(pm - mx) : 0.f;
            float ssum = wsum(e);
            float attn = e / ssum;

            if (lane < 30) {
                size_t o = ((size_t)b * NP + n) * KN + lane;
                g_AJ[o] = make_float2(attn, __int_as_float(tj[lane]));
            }

            float px = pxv[p], py = pyv[p], pz = pzv[p];
            float qd0 = m0[0]*px*px + m0[3]*py*py + m0[5]*pz*pz +
                        2.f*(m0[1]*px*py + m0[2]*px*pz + m0[4]*py*pz);
            float qd1 = m1[0]*px*px + m1[3]*py*py + m1[5]*pz*pz +
                        2.f*(m1[1]*px*py + m1[2]*px*pz + m1[4]*py*pz);
            float s1g0 = 0.f, s2g0 = 0.f, s1g1 = 0.f, s2g1 = 0.f;
            if (lane < 30) {
                int j = tj[lane];
                float a = attn, a2 = attn * attn;
                s1g0 = a * (srow[j]       - (dg00*px + dg01*py + dg02*pz));
                s1g1 = a * (srow[120 + j] - (dg10*px + dg11*py + dg12*pz));
                const float* sd0 = sdv + j * 3;
                const float* sd1 = sdv + (120 + j) * 3;
                s2g0 = a2 * (ssv[j]       - 2.f*(sd0[0]*px + sd0[1]*py + sd0[2]*pz) + qd0);
                s2g1 = a2 * (ssv[120 + j] - 2.f*(sd1[0]*px + sd1[1]*py + sd1[2]*pz) + qd1);
            }
            s1g0 = wsum(s1g0); s2g0 = wsum(s2g0); s1g1 = wsum(s1g1); s2g1 = wsum(s2g1);
            if (lane == 0) { acc0 += s1g0; acc1 += s2g0; acc2 += s1g1; acc3 += s2g1; }
            __syncwarp();
        }
    }

    if (lane == 0) {
        atomicAdd(&bacc[0], acc0); atomicAdd(&bacc[1], acc1);
        atomicAdd(&bacc[2], acc2); atomicAdd(&bacc[3], acc3);
    }
    __syncthreads();
    if (tid < 4) atomicAdd(&g_stats[b][tid >> 1][tid & 1], bacc[tid]);
}

// ----------------- K3 (combined attn+idx loads) ---------
#define P_S    0
#define P_MLP  61440
#define P_TAJ  64512
#define S3_TOTAL 79872
#define GRP 5
#define K3_WARPS_TOTAL 2368

__global__ void __launch_bounds__(512, 2)
k3_out(const float* __restrict__ points,
       const float* __restrict__ feature,
       const float* __restrict__ conv_w,
       const float* __restrict__ gamma,
       const float* __restrict__ beta,
       const float* __restrict__ mlp_w,
       const float* __restrict__ mlp_b,
       float* __restrict__ out)
{
    extern __shared__ unsigned char sm[];
    float* Ss = (float*)(sm + P_S);
    float* mw = (float*)(sm + P_MLP);
    float2* taj = (float2*)(sm + P_TAJ);
    __shared__ float s_ms[4];
    __shared__ float s_A[128];
    __shared__ float s_Bv[128];

    int tid = threadIdx.x, b = blockIdx.y;
    if (tid < 2) {
        double cnt = 64.0 * 30.0 * 8192.0;
        double mu = g_stats[b][tid][0] / cnt;
        double var = g_stats[b][tid][1] / cnt - mu * mu;
        s_ms[tid] = (float)mu;
        s_ms[2 + tid] = (float)(1.0 / sqrt(var + 1e-5));
    }
    __syncthreads();
    if (tid < 128) {
        int g = tid >> 6;
        float A = s_ms[2 + g] * __ldg(&gamma[tid]);
        s_A[tid] = A;
        s_Bv[tid] = __ldg(&beta[tid]) - s_ms[g] * A;
    }
    for (int i = tid; i < 768; i += 512) mw[i] = mlp_w[i];
    __syncthreads();
    {
        float4* dst = (float4*)Ss;
        const float4* srcp = (const float4*)&g_S[b][0];
        const float4* A4 = (const float4*)s_A;
        for (int i = tid; i < 3840; i += 512) {
            float4 v = srcp[i];
            float4 a = A4[i & 31];
            v.x *= a.x; v.y *= a.y; v.z *= a.z; v.w *= a.w;
            dst[i] = v;
        }
    }
    __syncthreads();

    int w = tid >> 5, lane = tid & 31;
    int gw = blockIdx.x * 16 + w;

    uint32_t taj_u = (uint32_t)__cvta_generic_to_shared(taj);
#pragma unroll
    for (int t4 = 0; t4 < 4; t4++) {
        int n = gw + t4 * K3_WARPS_TOTAL;
        if (n < NP && lane < 30) {
            size_t o = ((size_t)b * NP + n) * KN + lane;
            uint32_t off = ((w * 4 + t4) * KN + lane) * 8;
            cpa8(taj_u + off, (const void*)(g_AJ + o));
        }
        cpa_commit();
    }

    float A[4], Bv[4], nAD[4][3], wo[3][4], wf[3][4];
#pragma unroll
    for (int q = 0; q < 4; q++) {
        int o = 4 * lane + q;
        A[q] = s_A[o];
        Bv[q] = s_Bv[o];
        nAD[q][0] = -A[q] * __ldg(&conv_w[o * 131 + 128]);
        nAD[q][1] = -A[q] * __ldg(&conv_w[o * 131 + 129]);
        nAD[q][2] = -A[q] * __ldg(&conv_w[o * 131 + 130]);
#pragma unroll
        for (int t = 0; t < 3; t++) {
            wo[t][q] = mw[t * 256 + o];
            wf[t][q] = mw[t * 256 + 128 + o];
        }
    }
    float b0 = __ldg(&mlp_b[0]), b1 = __ldg(&mlp_b[1]), b2 = __ldg(&mlp_b[2]);
    const float4* S4 = (const float4*)Ss;
    const float4* f4 = (const float4*)feature;

#pragma unroll
    for (int t4 = 0; t4 < 4; t4++) {
        int n = gw + t4 * K3_WARPS_TOTAL;
        if (n >= NP) break;
        if (t4 == 0) cpa_wait<3>();
        else if (t4 == 1) cpa_wait<2>();
        else if (t4 == 2) cpa_wait<1>();
        else cpa_wait<0>();
        __syncwarp();

        const float2* tajw = taj + (w * 4 + t4) * KN;

        float px = __ldg(&points[((size_t)b * NP + n) * 3 + 0]);
        float py = __ldg(&points[((size_t)b * NP + n) * 3 + 1]);
        float pz = __ldg(&points[((size_t)b * NP + n) * 3 + 2]);
        float4 fv = f4[((size_t)b * NP + n) * 32 + lane];

        float edp[4];
#pragma unroll
        for (int q = 0; q < 4; q++) edp[q] = nAD[q][0]*px + nAD[q][1]*py + nAD[q][2]*pz;

        float mxv[4];
#pragma unroll
        for (int q = 0; q < 4; q++) mxv[q] = -1e30f;

#pragma unroll
        for (int g5 = 0; g5 < KN / GRP; g5++) {
            float a5[GRP]; int j5[GRP]; float4 s5[GRP];
#pragma unroll
            for (int t = 0; t < GRP; t++) {
                float2 aj = tajw[g5 * GRP + t];
                a5[t] = aj.x;
                j5[t] = __float_as_int(aj.y);
            }
#pragma unroll
            for (int t = 0; t < GRP; t++) s5[t] = S4[j5[t] * 32 + lane];
#pragma unroll
            for (int t = 0; t < GRP; t++) {
                float a = a5[t];
                float v0 = fmaf(a, s5[t].x, a * edp[0]); mxv[0] = fmaxf(mxv[0], v0);
                float v1 = fmaf(a, s5[t].y, a * edp[1]); mxv[1] = fmaxf(mxv[1], v1);
                float v2 = fmaf(a, s5[t].z, a * edp[2]); mxv[2] = fmaxf(mxv[2], v2);
                float v3 = fmaf(a, s5[t].w, a * edp[3]); mxv[3] = fmaxf(mxv[3], v3);
            }
        }

        float o0 = 0.f, o1 = 0.f, o2 = 0.f;
        float fr[4] = { fv.x, fv.y, fv.z, fv.w };
#pragma unroll
        for (int q = 0; q < 4; q++) {
            float z = mxv[q] + Bv[q];
            float ym = (z >= 0.f) ? z : 0.2f * z;
            o0 = fmaf(wo[0][q], ym, fmaf(wf[0][q], fr[q], o0));
            o1 = fmaf(wo[1][q], ym, fmaf(wf[1][q], fr[q], o1));
            o2 = fmaf(wo[2][q], ym, fmaf(wf[2][q], fr[q], o2));
        }
        o0 = wsum(o0); o1 = wsum(o1); o2 = wsum(o2);
        if (lane == 0) {
            out[((size_t)b * 3 + 0) * NP + n] = o0 + b0;
            out[((size_t)b * 3 + 1) * NP + n] = o1 + b1;
            out[((size_t)b * 3 + 2) * NP + n] = o2 + b2;
        }
    }
}

// ----------------- host: numpy RandomState(1234) key indices -----------------
static void compute_key_indices(int* outv) {
    static const int NMT = 624;
    unsigned mt[624]; int mti;
    mt[0] = 1234u;
    for (int i = 1; i < NMT; i++)
        mt[i] = 1812433253u * (mt[i-1] ^ (mt[i-1] >> 30)) + (unsigned)i;
    mti = NMT;
    auto nxt = [&]() -> unsigned {
        if (mti >= NMT) {
            for (int k = 0; k < NMT; k++) {
                unsigned y = (mt[k] & 0x80000000u) | (mt[(k+1) % NMT] & 0x7fffffffu);
                mt[k] = mt[(k+397) % NMT] ^ (y >> 1) ^ ((y & 1u) ? 2567483615u : 0u);
            }
            mti = 0;
        }
        unsigned y = mt[mti++];
        y ^= y >> 11; y ^= (y << 7) & 2636928640u; y ^= (y << 15) & 4022730752u; y ^= y >> 18;
        return y;
    };
    auto interval = [&](unsigned mx) -> unsigned {
        unsigned mask = mx;
        mask |= mask >> 1; mask |= mask >> 2; mask |= mask >> 4;
        mask |= mask >> 8; mask |= mask >> 16;
        unsigned v;
        while ((v = nxt() & mask) > mx) {}
        return v;
    };
    static int arr[NP];
    for (int i = 0; i < NP; i++) arr[i] = i;
    for (int i = NP - 1; i > 0; i--) {
        unsigned j = interval((unsigned)i);
        int t = arr[i]; arr[i] = arr[j]; arr[j] = t;
    }
    for (int i = 0; i < KS; i++) outv[i] = arr[i];
}

extern "C" void kernel_launch(void* const* d_in, const int* in_sizes, int n_in,
                              void* d_out, int out_size) {
    const float* points  = (const float*)d_in[0];
    const float* feature = (const float*)d_in[1];
    const float* inst    = (const float*)d_in[2];
    const float* w1      = (const float*)d_in[3];
    const float* w2      = (const float*)d_in[4];
    const float* conv_w  = (const float*)d_in[5];
    const float* gamma   = (const float*)d_in[6];
    const float* beta    = (const float*)d_in[7];
    const float* mlp_w   = (const float*)d_in[8];
    const float* mlp_b   = (const float*)d_in[9];
    float* out = (float*)d_out;

    KIdx kid;
    compute_key_indices(kid.v);

    cudaFuncSetAttribute(k1_attn, cudaFuncAttributeMaxDynamicSharedMemorySize, S1_TOTAL);
    cudaFuncSetAttribute(k3_out,  cudaFuncAttributeMaxDynamicSharedMemorySize, S3_TOTAL);

    k_tr<<<dim3(5, 5), dim3(32, 32)>>>(conv_w);
    k0_prep<<<dim3(KS, NB), 128>>>(points, feature, inst, kid);
    k1_attn<<<dim3(256, NB), 256, S1_TOTAL>>>(points, inst, w1, w2);
    k3_out<<<dim3(148, NB), 512, S3_TOTAL>>>(points, feature, conv_w, gamma, beta,
                                             mlp_w, mlp_b, out);
}

// round 16
// speedup vs baseline: 1.0432x; 1.0432x over previous
#include <cuda_runtime.h>
#include <stdint.h>

#define NB 2
#define NP 8192
#define KS 120
#define KN 30
#define WST 33   // w1s/w2s row stride: odd => conflict-free column access

struct KIdx { int v[KS]; };

// ----------------- device scratch -----------------
__device__ __align__(16) float g_WT[131 * 128];       // transposed conv_w: [c][o]
__device__ __align__(16) float g_gnT[NB][128 * KS];   // [b][c*120+j]
__device__ __align__(16) float g_S[NB][KS * 128];     // [b][j*128+o]
__device__ float  g_Srow[NB][2][KS];
__device__ float  g_SSv [NB][2][KS];
__device__ float  g_SDv [NB][2][KS][3];
__device__ float  g_Dg[2][3];
__device__ float  g_M [2][6];
__device__ double g_stats[NB][2][2];
__device__ __align__(8) float2 g_AJ[(size_t)NB * NP * KN];   // (attn, bitcast j)

__device__ __forceinline__ float wsum(float x) {
#pragma unroll
    for (int d = 16; d; d >>= 1) x += __shfl_xor_sync(0xffffffffu, x, d);
    return x;
}
__device__ __forceinline__ float wmax(float x) {
#pragma unroll
    for (int d = 16; d; d >>= 1) x = fmaxf(x, __shfl_xor_sync(0xffffffffu, x, d));
    return x;
}
__device__ __forceinline__ unsigned ord32(float d) {
    unsigned u = __float_as_uint(d);
    return (u & 0x80000000u) ? ~u : (u | 0x80000000u);
}

#define ICNT(acc, e, k) \
    asm("{.reg .pred p; setp.gt.u32 p, %1, %2; @p add.s32 %0, %0, 1;}" \
        : "+r"(acc) : "r"(e), "r"(k))

template<int N> __device__ __forceinline__ void cpa_wait() {
    asm volatile("cp.async.wait_group %0;" :: "n"(N) : "memory");
}
__device__ __forceinline__ void cpa_commit() {
    asm volatile("cp.async.commit_group;" ::: "memory");
}
__device__ __forceinline__ void cpa8(uint32_t dst, const void* src) {
    asm volatile("cp.async.ca.shared.global [%0], [%1], 8;" :: "r"(dst), "l"(src) : "memory");
}

// ----------------- K_TR: transpose conv_w + aux constants -----------------
__global__ void k_tr(const float* __restrict__ conv_w)
{
    if (blockIdx.y == 4) {
        if (blockIdx.x != 0) return;
        int t = threadIdx.y * 32 + threadIdx.x;
        if (t < 6) {
            int g = t / 3, c = t % 3;
            float a = 0.f;
            for (int o = g * 64; o < g * 64 + 64; o++) a += __ldg(&conv_w[o * 131 + 128 + c]);
            g_Dg[g][c] = a;
        }
        if (t >= 32 && t < 44) {
            int u = t - 32, g = u / 6, e = u % 6;
            const int ti[6] = {0,0,0,1,1,2}, tj2[6] = {0,1,2,1,2,2};
            float a = 0.f;
            for (int o = g * 64; o < g * 64 + 64; o++)
                a += __ldg(&conv_w[o * 131 + 128 + ti[e]]) * __ldg(&conv_w[o * 131 + 128 + tj2[e]]);
            g_M[g][e] = a;
        }
        if (t == 64) { double* z = &g_stats[0][0][0]; for (int x = 0; x < 8; x++) z[x] = 0.0; }
        return;
    }
    __shared__ float tile[32][33];
    int c = blockIdx.x * 32 + threadIdx.x;
    int o = blockIdx.y * 32 + threadIdx.y;
    if (c < 131) tile[threadIdx.y][threadIdx.x] = conv_w[o * 131 + c];
    __syncthreads();
    int c2 = blockIdx.x * 32 + threadIdx.y;
    int o2 = blockIdx.y * 32 + threadIdx.x;
    if (c2 < 131) g_WT[c2 * 128 + o2] = tile[threadIdx.x][threadIdx.y];
}

// ----------------- K0 -----------------
__global__ void k0_prep(const float* __restrict__ points,
                        const float* __restrict__ feature,
                        const float* __restrict__ inst, KIdx kid)
{
    int b = blockIdx.y, j = blockIdx.x, tid = threadIdx.x;
    __shared__ float frow[131];
    __shared__ float red[5][128];
    __shared__ float rsum[4];

    int src = kid.v[j];
    size_t rb = (size_t)b * NP + src;
    float v = inst[rb * 128 + tid];
    frow[tid] = feature[rb * 128 + tid];
    if (tid < 3) frow[128 + tid] = points[rb * 3 + tid];

    float sq = v * v;
#pragma unroll
    for (int d = 16; d; d >>= 1) sq += __shfl_xor_sync(0xffffffffu, sq, d);
    if ((tid & 31) == 0) rsum[tid >> 5] = sq;
    __syncthreads();
    float rn = 1.0f / sqrtf(rsum[0] + rsum[1] + rsum[2] + rsum[3]);
    g_gnT[b][tid * KS + j] = v * rn;

    float s = 0.f;
#pragma unroll 16
    for (int c = 0; c < 131; c++) s = fmaf(g_WT[c * 128 + tid], frow[c], s);
    g_S[b][j * 128 + tid] = s;

    float d0 = g_WT[128 * 128 + tid], d1 = g_WT[129 * 128 + tid], d2 = g_WT[130 * 128 + tid];
    red[0][tid] = s;      red[1][tid] = s * s;
    red[2][tid] = s * d0; red[3][tid] = s * d1; red[4][tid] = s * d2;
    __syncthreads();

    if (tid < 10) {
        int q = tid >> 1, g = tid & 1;
        float a = 0.f;
        for (int t = 0; t < 64; t++) a += red[q][g * 64 + t];
        if (q == 0)      g_Srow[b][g][j] = a;
        else if (q == 1) g_SSv[b][g][j]  = a;
        else             g_SDv[b][g][j][q - 2] = a;
    }
}

// ----------------- K1: gnT via L1 (no smem table), 3 blocks/SM -----------
#define O_W1    0
#define O_W2    3960
#define O_SROW  7920
#define O_SSV   8880
#define O_SDV   9840
#define O_FNB   12720
#define O_SELK  29104
#define O_SELV  31024
#define O_SELJ  31984
#define O_TOPD  32944
#define O_TOPJ  33904
#define O_AB    34864
#define O_BACC  35888
#define S1_TOTAL 35920

__global__ void __launch_bounds__(256, 3)
k1_attn(const float* __restrict__ points,
        const float* __restrict__ inst,
        const float* __restrict__ w1g,
        const float* __restrict__ w2g)
{
    extern __shared__ unsigned char sm[];
    float* w1s = (float*)(sm + O_W1);
    float* w2s = (float*)(sm + O_W2);
    float* srow = (float*)(sm + O_SROW);
    float* ssv  = (float*)(sm + O_SSV);
    float* sdv  = (float*)(sm + O_SDV);
    float* fnb  = (float*)(sm + O_FNB);
    unsigned long long* selkB = (unsigned long long*)(sm + O_SELK);
    float* selvB = (float*)(sm + O_SELV);
    int*   seljB = (int*)(sm + O_SELJ);
    float* topd = (float*)(sm + O_TOPD);
    int*   topj = (int*)(sm + O_TOPJ);
    float* ab   = (float*)(sm + O_AB);
    double* bacc = (double*)(sm + O_BACC);

    int tid = threadIdx.x, b = blockIdx.y;
    {
        for (int i = tid; i < 30 * WST; i += 256) {
            int r = i / WST, c = i % WST;
            w1s[i] = (c < 30) ? w1g[r * 30 + c] : 0.f;
            w2s[i] = (c < 30) ? w2g[r * 30 + c] : 0.f;
        }
        const float* a0 = &g_Srow[b][0][0]; const float* a1 = &g_SSv[b][0][0];
        for (int i = tid; i < 240; i += 256) { srow[i] = a0[i]; ssv[i] = a1[i]; }
        const float* a2 = &g_SDv[b][0][0][0];
        for (int i = tid; i < 720; i += 256) sdv[i] = a2[i];
        if (tid < 4) bacc[tid] = 0.0;
    }
    __syncthreads();

    int w = tid >> 5, lane = tid & 31;
    int jl = lane < 30 ? lane : 29;
    int n0 = (blockIdx.x * 8 + w) * 4;
    unsigned long long* selkW = selkB + w * KN;
    float* selvW = selvB + w * KN;
    int*   seljW = seljB + w * KN;
    float* td = topd + w * KN;
    int*   tj = topj + w * KN;
    float* abw = ab + w * 32;
    float* fw = fnb + w * 4 * 128;

    float pxv[4], pyv[4], pzv[4];
#pragma unroll
    for (int p = 0; p < 4; p++) {
        pxv[p] = __ldg(&points[((size_t)b * NP + n0 + p) * 3 + 0]);
        pyv[p] = __ldg(&points[((size_t)b * NP + n0 + p) * 3 + 1]);
        pzv[p] = __ldg(&points[((size_t)b * NP + n0 + p) * 3 + 2]);
    }

    const float4* ip = (const float4*)inst;
#pragma unroll
    for (int p = 0; p < 4; p++) {
        float4 v = ip[((size_t)b * NP + n0 + p) * 32 + lane];
        float rn = 1.0f / sqrtf(wsum(v.x*v.x + v.y*v.y + v.z*v.z + v.w*v.w));
        ((float4*)(fw + p * 128))[lane] = make_float4(v.x*rn, v.y*rn, v.z*rn, v.w*rn);
    }
    __syncwarp();

    // dots (arithmetic order identical; gnT read from global via L1)
    float av[4][4];
#pragma unroll
    for (int p = 0; p < 4; p++)
#pragma unroll
        for (int q = 0; q < 4; q++) av[p][q] = 0.f;

    const float4* gnT4 = (const float4*)&g_gnT[b][0];
    const float4* f4p[4] = { (const float4*)(fw), (const float4*)(fw + 128),
                             (const float4*)(fw + 256), (const float4*)(fw + 384) };
#pragma unroll 4
    for (int c4 = 0; c4 < 32; c4++) {
        float4 a[4];
#pragma unroll
        for (int p = 0; p < 4; p++) a[p] = f4p[p][c4];
#pragma unroll
        for (int r = 0; r < 4; r++) {
            float4 gv = __ldg(&gnT4[(c4 * 4 + r) * 30 + jl]);
#pragma unroll
            for (int p = 0; p < 4; p++) {
                float s = (r == 0) ? a[p].x : (r == 1) ? a[p].y : (r == 2) ? a[p].z : a[p].w;
                av[p][0] = fmaf(s, gv.x, av[p][0]);
                av[p][1] = fmaf(s, gv.y, av[p][1]);
                av[p][2] = fmaf(s, gv.z, av[p][2]);
                av[p][3] = fmaf(s, gv.w, av[p][3]);
            }
        }
    }

    float dg00 = g_Dg[0][0], dg01 = g_Dg[0][1], dg02 = g_Dg[0][2];
    float dg10 = g_Dg[1][0], dg11 = g_Dg[1][1], dg12 = g_Dg[1][2];
    float m0[6], m1[6];
#pragma unroll
    for (int e = 0; e < 6; e++) { m0[e] = g_M[0][e]; m1[e] = g_M[1][e]; }

    double acc0 = 0, acc1 = 0, acc2 = 0, acc3 = 0;

#pragma unroll
    for (int p = 0; p < 4; p++) {
        int n = n0 + p;
        float dd0 = av[p][0] - 1.0f, dd1 = av[p][1] - 1.0f,
              dd2 = av[p][2] - 1.0f, dd3 = av[p][3] - 1.0f;
        unsigned v0 = (lane < 30) ? ord32(dd0) : 0u;
        unsigned v1 = (lane < 30) ? ord32(dd1) : 0u;
        unsigned v2 = (lane < 30) ? ord32(dd2) : 0u;
        unsigned v3 = (lane < 30) ? ord32(dd3) : 0u;

        // binary search for the 30th-largest value T (exact)
        unsigned T = 0u;
#pragma unroll
        for (int bit = 31; bit >= 0; bit--) {
            unsigned cand = T | (1u << bit);
            unsigned cm1 = cand - 1u;
            int c = 0;
            ICNT(c, v0, cm1); ICNT(c, v1, cm1);
            ICNT(c, v2, cm1); ICNT(c, v3, cm1);
            c = __reduce_add_sync(0xffffffffu, c);
            if (c >= KN) T = cand;
        }

        bool gt0 = v0 > T, gt1 = v1 > T, gt2 = v2 > T, gt3 = v3 > T;
        bool eq0 = v0 == T, eq1 = v1 == T, eq2 = v2 == T, eq3 = v3 == T;
        int G = __reduce_add_sync(0xffffffffu,
                                  (int)gt0 + (int)gt1 + (int)gt2 + (int)gt3);
        int Bq = KN - G;

        unsigned e0 = __ballot_sync(0xffffffffu, eq0);
        unsigned e1 = __ballot_sync(0xffffffffu, eq1);
        unsigned e2 = __ballot_sync(0xffffffffu, eq2);
        unsigned e3 = __ballot_sync(0xffffffffu, eq3);
        unsigned lt = (1u << lane) - 1u;
        int el0 = __popc(e0 & lt) + __popc(e1 & lt) + __popc(e2 & lt) + __popc(e3 & lt);
        int el1 = el0 + (int)eq0;
        int el2 = el1 + (int)eq1;
        int el3 = el2 + (int)eq2;
        bool sel0 = gt0 || (eq0 && el0 < Bq);
        bool sel1 = gt1 || (eq1 && el1 < Bq);
        bool sel2 = gt2 || (eq2 && el2 < Bq);
        bool sel3 = gt3 || (eq3 && el3 < Bq);

        unsigned s0 = __ballot_sync(0xffffffffu, sel0);
        unsigned s1 = __ballot_sync(0xffffffffu, sel1);
        unsigned s2 = __ballot_sync(0xffffffffu, sel2);
        unsigned s3 = __ballot_sync(0xffffffffu, sel3);
        int q0 = __popc(s0 & lt) + __popc(s1 & lt) + __popc(s2 & lt) + __popc(s3 & lt);
        int q1 = q0 + (int)sel0;
        int q2 = q1 + (int)sel1;
        int q3 = q2 + (int)sel2;
        int jb = 4 * lane;
        if (sel0) { selkW[q0] = ((unsigned long long)v0 << 32) | (unsigned)(KS-1-jb);
                    selvW[q0] = dd0; seljW[q0] = jb; }
        if (sel1) { selkW[q1] = ((unsigned long long)v1 << 32) | (unsigned)(KS-2-jb);
                    selvW[q1] = dd1; seljW[q1] = jb + 1; }
        if (sel2) { selkW[q2] = ((unsigned long long)v2 << 32) | (unsigned)(KS-3-jb);
                    selvW[q2] = dd2; seljW[q2] = jb + 2; }
        if (sel3) { selkW[q3] = ((unsigned long long)v3 << 32) | (unsigned)(KS-4-jb);
                    selvW[q3] = dd3; seljW[q3] = jb + 3; }
        __syncwarp();

        // rank the 30 survivors among themselves (u64 keys, all distinct)
        if (lane < 30) {
            unsigned long long mykey = selkW[lane];
            int rank = 0;
#pragma unroll 6
            for (int k = 0; k < KN; k++) rank += (int)(selkW[k] > mykey);
            td[rank] = selvW[lane];
            tj[rank] = seljW[lane];
        }
        __syncwarp();

        // kpam layer 1 + relu (stride-33 rows: conflict-free)
        float a1v = 0.f;
        {
            const float* wr = w1s + jl * WST;
            for (int k = 0; k < KN; k++) a1v = fmaf(td[k], wr[k], a1v);
            a1v = fmaxf(a1v, 0.f);
        }
        abw[lane] = a1v;
        __syncwarp();
        float pv = 0.f;
        {
            const float* wr = w2s + jl * WST;
            for (int o = 0; o < KN; o++) pv = fmaf(abw[o], wr[o], pv);
        }
        float pm = (lane < 30) ? pv : -1e30f;
        float mx = wmax(pm);
        float e = (lane < 30) ? __expf(pm - mx) : 0.f;
        float ssum = wsum(e);
        float attn = e / ssum;

        if (lane < 30) {
            size_t o = ((size_t)b * NP + n) * KN + lane;
            g_AJ[o] = make_float2(attn, __int_as_float(tj[lane]));
        }

        float px = pxv[p], py = pyv[p], pz = pzv[p];
        float qd0 = m0[0]*px*px + m0[3]*py*py + m0[5]*pz*pz +
                    2.f*(m0[1]*px*py + m0[2]*px*pz + m0[4]*py*pz);
        float qd1 = m1[0]*px*px + m1[3]*py*py + m1[5]*pz*pz +
                    2.f*(m1[1]*px*py + m1[2]*px*pz + m1[4]*py*pz);
        float s1g0 = 0.f, s2g0 = 0.f, s1g1 = 0.f, s2g1 = 0.f;
        if (lane < 30) {
            int j = tj[lane];
            float a = attn, a2 = attn * attn;
            s1g0 = a * (srow[j]       - (dg00*px + dg01*py + dg02*pz));
            s1g1 = a * (srow[120 + j] - (dg10*px + dg11*py + dg12*pz));
            const float* sd0 = sdv + j * 3;
            const float* sd1 = sdv + (120 + j) * 3;
            s2g0 = a2 * (ssv[j]       - 2.f*(sd0[0]*px + sd0[1]*py + sd0[2]*pz) + qd0);
            s2g1 = a2 * (ssv[120 + j] - 2.f*(sd1[0]*px + sd1[1]*py + sd1[2]*pz) + qd1);
        }
        s1g0 = wsum(s1g0); s2g0 = wsum(s2g0); s1g1 = wsum(s1g1); s2g1 = wsum(s2g1);
        if (lane == 0) { acc0 += s1g0; acc1 += s2g0; acc2 += s1g1; acc3 += s2g1; }
        __syncwarp();
    }

    if (lane == 0) {
        atomicAdd(&bacc[0], acc0); atomicAdd(&bacc[1], acc1);
        atomicAdd(&bacc[2], acc2); atomicAdd(&bacc[3], acc3);
    }
    __syncthreads();
    if (tid < 4) atomicAdd(&g_stats[b][tid >> 1][tid & 1], bacc[tid]);
}

// ----------------- K3 (combined attn+idx loads) ---------
#define P_S    0
#define P_MLP  61440
#define P_TAJ  64512
#define S3_TOTAL 79872
#define GRP 5
#define K3_WARPS_TOTAL 2368

__global__ void __launch_bounds__(512, 2)
k3_out(const float* __restrict__ points,
       const float* __restrict__ feature,
       const float* __restrict__ conv_w,
       const float* __restrict__ gamma,
       const float* __restrict__ beta,
       const float* __restrict__ mlp_w,
       const float* __restrict__ mlp_b,
       float* __restrict__ out)
{
    extern __shared__ unsigned char sm[];
    float* Ss = (float*)(sm + P_S);
    float* mw = (float*)(sm + P_MLP);
    float2* taj = (float2*)(sm + P_TAJ);
    __shared__ float s_ms[4];
    __shared__ float s_A[128];
    __shared__ float s_Bv[128];

    int tid = threadIdx.x, b = blockIdx.y;
    if (tid < 2) {
        double cnt = 64.0 * 30.0 * 8192.0;
        double mu = g_stats[b][tid][0] / cnt;
        double var = g_stats[b][tid][1] / cnt - mu * mu;
        s_ms[tid] = (float)mu;
        s_ms[2 + tid] = (float)(1.0 / sqrt(var + 1e-5));
    }
    __syncthreads();
    if (tid < 128) {
        int g = tid >> 6;
        float A = s_ms[2 + g] * __ldg(&gamma[tid]);
        s_A[tid] = A;
        s_Bv[tid] = __ldg(&beta[tid]) - s_ms[g] * A;
    }
    for (int i = tid; i < 768; i += 512) mw[i] = mlp_w[i];
    __syncthreads();
    {
        float4* dst = (float4*)Ss;
        const float4* srcp = (const float4*)&g_S[b][0];
        const float4* A4 = (const float4*)s_A;
        for (int i = tid; i < 3840; i += 512) {
            float4 v = srcp[i];
            float4 a = A4[i & 31];
            v.x *= a.x; v.y *= a.y; v.z *= a.z; v.w *= a.w;
            dst[i] = v;
        }
    }
    __syncthreads();

    int w = tid >> 5, lane = tid & 31;
    int gw = blockIdx.x * 16 + w;

    uint32_t taj_u = (uint32_t)__cvta_generic_to_shared(taj);
#pragma unroll
    for (int t4 = 0; t4 < 4; t4++) {
        int n = gw + t4 * K3_WARPS_TOTAL;
        if (n < NP && lane < 30) {
            size_t o = ((size_t)b * NP + n) * KN + lane;
            uint32_t off = ((w * 4 + t4) * KN + lane) * 8;
            cpa8(taj_u + off, (const void*)(g_AJ + o));
        }
        cpa_commit();
    }

    float A[4], Bv[4], nAD[4][3], wo[3][4], wf[3][4];
#pragma unroll
    for (int q = 0; q < 4; q++) {
        int o = 4 * lane + q;
        A[q] = s_A[o];
        Bv[q] = s_Bv[o];
        nAD[q][0] = -A[q] * __ldg(&conv_w[o * 131 + 128]);
        nAD[q][1] = -A[q] * __ldg(&conv_w[o * 131 + 129]);
        nAD[q][2] = -A[q] * __ldg(&conv_w[o * 131 + 130]);
#pragma unroll
        for (int t = 0; t < 3; t++) {
            wo[t][q] = mw[t * 256 + o];
            wf[t][q] = mw[t * 256 + 128 + o];
        }
    }
    float b0 = __ldg(&mlp_b[0]), b1 = __ldg(&mlp_b[1]), b2 = __ldg(&mlp_b[2]);
    const float4* S4 = (const float4*)Ss;
    const float4* f4 = (const float4*)feature;

#pragma unroll
    for (int t4 = 0; t4 < 4; t4++) {
        int n = gw + t4 * K3_WARPS_TOTAL;
        if (n >= NP) break;
        if (t4 == 0) cpa_wait<3>();
        else if (t4 == 1) cpa_wait<2>();
        else if (t4 == 2) cpa_wait<1>();
        else cpa_wait<0>();
        __syncwarp();

        const float2* tajw = taj + (w * 4 + t4) * KN;

        float px = __ldg(&points[((size_t)b * NP + n) * 3 + 0]);
        float py = __ldg(&points[((size_t)b * NP + n) * 3 + 1]);
        float pz = __ldg(&points[((size_t)b * NP + n) * 3 + 2]);
        float4 fv = f4[((size_t)b * NP + n) * 32 + lane];

        float edp[4];
#pragma unroll
        for (int q = 0; q < 4; q++) edp[q] = nAD[q][0]*px + nAD[q][1]*py + nAD[q][2]*pz;

        float mxv[4];
#pragma unroll
        for (int q = 0; q < 4; q++) mxv[q] = -1e30f;

#pragma unroll
        for (int g5 = 0; g5 < KN / GRP; g5++) {
            float a5[GRP]; int j5[GRP]; float4 s5[GRP];
#pragma unroll
            for (int t = 0; t < GRP; t++) {
                float2 aj = tajw[g5 * GRP + t];
                a5[t] = aj.x;
                j5[t] = __float_as_int(aj.y);
            }
#pragma unroll
            for (int t = 0; t < GRP; t++) s5[t] = S4[j5[t] * 32 + lane];
#pragma unroll
            for (int t = 0; t < GRP; t++) {
                float a = a5[t];
                float v0 = fmaf(a, s5[t].x, a * edp[0]); mxv[0] = fmaxf(mxv[0], v0);
                float v1 = fmaf(a, s5[t].y, a * edp[1]); mxv[1] = fmaxf(mxv[1], v1);
                float v2 = fmaf(a, s5[t].z, a * edp[2]); mxv[2] = fmaxf(mxv[2], v2);
                float v3 = fmaf(a, s5[t].w, a * edp[3]); mxv[3] = fmaxf(mxv[3], v3);
            }
        }

        float o0 = 0.f, o1 = 0.f, o2 = 0.f;
        float fr[4] = { fv.x, fv.y, fv.z, fv.w };
#pragma unroll
        for (int q = 0; q < 4; q++) {
            float z = mxv[q] + Bv[q];
            float ym = (z >= 0.f) ? z : 0.2f * z;
            o0 = fmaf(wo[0][q], ym, fmaf(wf[0][q], fr[q], o0));
            o1 = fmaf(wo[1][q], ym, fmaf(wf[1][q], fr[q], o1));
            o2 = fmaf(wo[2][q], ym, fmaf(wf[2][q], fr[q], o2));
        }
        o0 = wsum(o0); o1 = wsum(o1); o2 = wsum(o2);
        if (lane == 0) {
            out[((size_t)b * 3 + 0) * NP + n] = o0 + b0;
            out[((size_t)b * 3 + 1) * NP + n] = o1 + b1;
            out[((size_t)b * 3 + 2) * NP + n] = o2 + b2;
        }
    }
}

// ----------------- host: numpy RandomState(1234) key indices -----------------
static void compute_key_indices(int* outv) {
    static const int NMT = 624;
    unsigned mt[624]; int mti;
    mt[0] = 1234u;
    for (int i = 1; i < NMT; i++)
        mt[i] = 1812433253u * (mt[i-1] ^ (mt[i-1] >> 30)) + (unsigned)i;
    mti = NMT;
    auto nxt = [&]() -> unsigned {
        if (mti >= NMT) {
            for (int k = 0; k < NMT; k++) {
                unsigned y = (mt[k] & 0x80000000u) | (mt[(k+1) % NMT] & 0x7fffffffu);
                mt[k] = mt[(k+397) % NMT] ^ (y >> 1) ^ ((y & 1u) ? 2567483615u : 0u);
            }
            mti = 0;
        }
        unsigned y = mt[mti++];
        y ^= y >> 11; y ^= (y << 7) & 2636928640u; y ^= (y << 15) & 4022730752u; y ^= y >> 18;
        return y;
    };
    auto interval = [&](unsigned mx) -> unsigned {
        unsigned mask = mx;
        mask |= mask >> 1; mask |= mask >> 2; mask |= mask >> 4;
        mask |= mask >> 8; mask |= mask >> 16;
        unsigned v;
        while ((v = nxt() & mask) > mx) {}
        return v;
    };
    static int arr[NP];
    for (int i = 0; i < NP; i++) arr[i] = i;
    for (int i = NP - 1; i > 0; i--) {
        unsigned j = interval((unsigned)i);
        int t = arr[i]; arr[i] = arr[j]; arr[j] = t;
    }
    for (int i = 0; i < KS; i++) outv[i] = arr[i];
}

extern "C" void kernel_launch(void* const* d_in, const int* in_sizes, int n_in,
                              void* d_out, int out_size) {
    const float* points  = (const float*)d_in[0];
    const float* feature = (const float*)d_in[1];
    const float* inst    = (const float*)d_in[2];
    const float* w1      = (const float*)d_in[3];
    const float* w2      = (const float*)d_in[4];
    const float* conv_w  = (const float*)d_in[5];
    const float* gamma   = (const float*)d_in[6];
    const float* beta    = (const float*)d_in[7];
    const float* mlp_w   = (const float*)d_in[8];
    const float* mlp_b   = (const float*)d_in[9];
    float* out = (float*)d_out;

    KIdx kid;
    compute_key_indices(kid.v);

    cudaFuncSetAttribute(k1_attn, cudaFuncAttributeMaxDynamicSharedMemorySize, S1_TOTAL);
    cudaFuncSetAttribute(k3_out,  cudaFuncAttributeMaxDynamicSharedMemorySize, S3_TOTAL);

    k_tr<<<dim3(5, 5), dim3(32, 32)>>>(conv_w);
    k0_prep<<<dim3(KS, NB), 128>>>(points, feature, inst, kid);
    k1_attn<<<dim3(256, NB), 256, S1_TOTAL>>>(points, inst, w1, w2);
    k3_out<<<dim3(148, NB), 512, S3_TOTAL>>>(points, feature, conv_w, gamma, beta,
                                             mlp_w, mlp_b, out);
}

// round 17
// speedup vs baseline: 1.2148x; 1.1644x over previous
#include <cuda_runtime.h>
#include <stdint.h>

#define NB 2
#define NP 8192
#define KS 120
#define KN 30
#define WST 33   // w1s/w2s row stride: odd => conflict-free column access

struct KIdx { int v[KS]; };

// ----------------- device scratch -----------------
__device__ __align__(16) float g_WT[131 * 128];       // transposed conv_w: [c][o]
__device__ __align__(16) float g_gnT[NB][128 * KS];   // [b][c*120+j]
__device__ __align__(16) float g_S[NB][KS * 128];     // [b][j*128+o]
__device__ float  g_Srow[NB][2][KS];
__device__ float  g_SSv [NB][2][KS];
__device__ float  g_SDv [NB][2][KS][3];
__device__ float  g_Dg[2][3];
__device__ float  g_M [2][6];
__device__ double g_stats[NB][2][2];
__device__ __align__(8) float2 g_AJ[(size_t)NB * NP * KN];   // (attn, bitcast j)

__device__ __forceinline__ float wsum(float x) {
#pragma unroll
    for (int d = 16; d; d >>= 1) x += __shfl_xor_sync(0xffffffffu, x, d);
    return x;
}
__device__ __forceinline__ float wmax(float x) {
#pragma unroll
    for (int d = 16; d; d >>= 1) x = fmaxf(x, __shfl_xor_sync(0xffffffffu, x, d));
    return x;
}
__device__ __forceinline__ unsigned ord32(float d) {
    unsigned u = __float_as_uint(d);
    return (u & 0x80000000u) ? ~u : (u | 0x80000000u);
}

#define ICNT(acc, e, k) \
    asm("{.reg .pred p; setp.gt.u32 p, %1, %2; @p add.s32 %0, %0, 1;}" \
        : "+r"(acc) : "r"(e), "r"(k))

template<int N> __device__ __forceinline__ void cpa_wait() {
    asm volatile("cp.async.wait_group %0;" :: "n"(N) : "memory");
}
__device__ __forceinline__ void cpa_commit() {
    asm volatile("cp.async.commit_group;" ::: "memory");
}
__device__ __forceinline__ void cpa8(uint32_t dst, const void* src) {
    asm volatile("cp.async.ca.shared.global [%0], [%1], 8;" :: "r"(dst), "l"(src) : "memory");
}

// ----------------- K_TR: transpose conv_w + aux constants -----------------
__global__ void k_tr(const float* __restrict__ conv_w)
{
    if (blockIdx.y == 4) {
        if (blockIdx.x != 0) return;
        int t = threadIdx.y * 32 + threadIdx.x;
        if (t < 6) {
            int g = t / 3, c = t % 3;
            float a = 0.f;
            for (int o = g * 64; o < g * 64 + 64; o++) a += __ldg(&conv_w[o * 131 + 128 + c]);
            g_Dg[g][c] = a;
        }
        if (t >= 32 && t < 44) {
            int u = t - 32, g = u / 6, e = u % 6;
            const int ti[6] = {0,0,0,1,1,2}, tj2[6] = {0,1,2,1,2,2};
            float a = 0.f;
            for (int o = g * 64; o < g * 64 + 64; o++)
                a += __ldg(&conv_w[o * 131 + 128 + ti[e]]) * __ldg(&conv_w[o * 131 + 128 + tj2[e]]);
            g_M[g][e] = a;
        }
        if (t == 64) { double* z = &g_stats[0][0][0]; for (int x = 0; x < 8; x++) z[x] = 0.0; }
        return;
    }
    __shared__ float tile[32][33];
    int c = blockIdx.x * 32 + threadIdx.x;
    int o = blockIdx.y * 32 + threadIdx.y;
    if (c < 131) tile[threadIdx.y][threadIdx.x] = conv_w[o * 131 + c];
    __syncthreads();
    int c2 = blockIdx.x * 32 + threadIdx.y;
    int o2 = blockIdx.y * 32 + threadIdx.x;
    if (c2 < 131) g_WT[c2 * 128 + o2] = tile[threadIdx.x][threadIdx.y];
}

// ----------------- K0 -----------------
__global__ void k0_prep(const float* __restrict__ points,
                        const float* __restrict__ feature,
                        const float* __restrict__ inst, KIdx kid)
{
    int b = blockIdx.y, j = blockIdx.x, tid = threadIdx.x;
    __shared__ float frow[131];
    __shared__ float red[5][128];
    __shared__ float rsum[4];

    int src = kid.v[j];
    size_t rb = (size_t)b * NP + src;
    float v = inst[rb * 128 + tid];
    frow[tid] = feature[rb * 128 + tid];
    if (tid < 3) frow[128 + tid] = points[rb * 3 + tid];

    float sq = v * v;
#pragma unroll
    for (int d = 16; d; d >>= 1) sq += __shfl_xor_sync(0xffffffffu, sq, d);
    if ((tid & 31) == 0) rsum[tid >> 5] = sq;
    __syncthreads();
    float rn = 1.0f / sqrtf(rsum[0] + rsum[1] + rsum[2] + rsum[3]);
    g_gnT[b][tid * KS + j] = v * rn;

    float s = 0.f;
#pragma unroll 16
    for (int c = 0; c < 131; c++) s = fmaf(g_WT[c * 128 + tid], frow[c], s);
    g_S[b][j * 128 + tid] = s;

    float d0 = g_WT[128 * 128 + tid], d1 = g_WT[129 * 128 + tid], d2 = g_WT[130 * 128 + tid];
    red[0][tid] = s;      red[1][tid] = s * s;
    red[2][tid] = s * d0; red[3][tid] = s * d1; red[4][tid] = s * d2;
    __syncthreads();

    if (tid < 10) {
        int q = tid >> 1, g = tid & 1;
        float a = 0.f;
        for (int t = 0; t < 64; t++) a += red[q][g * 64 + t];
        if (q == 0)      g_Srow[b][g][j] = a;
        else if (q == 1) g_SSv[b][g][j]  = a;
        else             g_SDv[b][g][j][q - 2] = a;
    }
}

// ----------------- K1: 128-thr blocks, 7/SM, single wave ------------------
#define O_W1    0
#define O_W2    3960
#define O_SROW  7920
#define O_SSV   8880
#define O_SDV   9840
#define O_FNB   12720
#define O_SELK  20912
#define O_SELV  21872
#define O_SELJ  22352
#define O_TOPD  22832
#define O_TOPJ  23312
#define O_AB    23792
#define O_BACC  24304
#define S1_TOTAL 24336

__global__ void __launch_bounds__(128, 7)
k1_attn(const float* __restrict__ points,
        const float* __restrict__ inst,
        const float* __restrict__ w1g,
        const float* __restrict__ w2g)
{
    extern __shared__ unsigned char sm[];
    float* w1s = (float*)(sm + O_W1);
    float* w2s = (float*)(sm + O_W2);
    float* srow = (float*)(sm + O_SROW);
    float* ssv  = (float*)(sm + O_SSV);
    float* sdv  = (float*)(sm + O_SDV);
    float* fnb  = (float*)(sm + O_FNB);
    unsigned long long* selkB = (unsigned long long*)(sm + O_SELK);
    float* selvB = (float*)(sm + O_SELV);
    int*   seljB = (int*)(sm + O_SELJ);
    float* topd = (float*)(sm + O_TOPD);
    int*   topj = (int*)(sm + O_TOPJ);
    float* ab   = (float*)(sm + O_AB);
    double* bacc = (double*)(sm + O_BACC);

    int tid = threadIdx.x, b = blockIdx.y;
    {
        for (int i = tid; i < 30 * WST; i += 128) {
            int r = i / WST, c = i % WST;
            w1s[i] = (c < 30) ? w1g[r * 30 + c] : 0.f;
            w2s[i] = (c < 30) ? w2g[r * 30 + c] : 0.f;
        }
        const float* a0 = &g_Srow[b][0][0]; const float* a1 = &g_SSv[b][0][0];
        for (int i = tid; i < 240; i += 128) { srow[i] = a0[i]; ssv[i] = a1[i]; }
        const float* a2 = &g_SDv[b][0][0][0];
        for (int i = tid; i < 720; i += 128) sdv[i] = a2[i];
        if (tid < 4) bacc[tid] = 0.0;
    }
    __syncthreads();

    int w = tid >> 5, lane = tid & 31;
    int jl = lane < 30 ? lane : 29;
    int n0 = (blockIdx.x * 4 + w) * 4;
    unsigned long long* selkW = selkB + w * KN;
    float* selvW = selvB + w * KN;
    int*   seljW = seljB + w * KN;
    float* td = topd + w * KN;
    int*   tj = topj + w * KN;
    float* abw = ab + w * 32;
    float* fw = fnb + w * 4 * 128;

    float pxv[4], pyv[4], pzv[4];
#pragma unroll
    for (int p = 0; p < 4; p++) {
        pxv[p] = __ldg(&points[((size_t)b * NP + n0 + p) * 3 + 0]);
        pyv[p] = __ldg(&points[((size_t)b * NP + n0 + p) * 3 + 1]);
        pzv[p] = __ldg(&points[((size_t)b * NP + n0 + p) * 3 + 2]);
    }

    const float4* ip = (const float4*)inst;
#pragma unroll
    for (int p = 0; p < 4; p++) {
        float4 v = ip[((size_t)b * NP + n0 + p) * 32 + lane];
        float rn = 1.0f / sqrtf(wsum(v.x*v.x + v.y*v.y + v.z*v.z + v.w*v.w));
        ((float4*)(fw + p * 128))[lane] = make_float4(v.x*rn, v.y*rn, v.z*rn, v.w*rn);
    }
    __syncwarp();

    // dots (arithmetic order identical; gnT read from global via L1)
    float av[4][4];
#pragma unroll
    for (int p = 0; p < 4; p++)
#pragma unroll
        for (int q = 0; q < 4; q++) av[p][q] = 0.f;

    const float4* gnT4 = (const float4*)&g_gnT[b][0];
    const float4* f4p[4] = { (const float4*)(fw), (const float4*)(fw + 128),
                             (const float4*)(fw + 256), (const float4*)(fw + 384) };
#pragma unroll 4
    for (int c4 = 0; c4 < 32; c4++) {
        float4 a[4];
#pragma unroll
        for (int p = 0; p < 4; p++) a[p] = f4p[p][c4];
#pragma unroll
        for (int r = 0; r < 4; r++) {
            float4 gv = __ldg(&gnT4[(c4 * 4 + r) * 30 + jl]);
#pragma unroll
            for (int p = 0; p < 4; p++) {
                float s = (r == 0) ? a[p].x : (r == 1) ? a[p].y : (r == 2) ? a[p].z : a[p].w;
                av[p][0] = fmaf(s, gv.x, av[p][0]);
                av[p][1] = fmaf(s, gv.y, av[p][1]);
                av[p][2] = fmaf(s, gv.z, av[p][2]);
                av[p][3] = fmaf(s, gv.w, av[p][3]);
            }
        }
    }

    float dg00 = g_Dg[0][0], dg01 = g_Dg[0][1], dg02 = g_Dg[0][2];
    float dg10 = g_Dg[1][0], dg11 = g_Dg[1][1], dg12 = g_Dg[1][2];
    float m0[6], m1[6];
#pragma unroll
    for (int e = 0; e < 6; e++) { m0[e] = g_M[0][e]; m1[e] = g_M[1][e]; }

    double acc0 = 0, acc1 = 0, acc2 = 0, acc3 = 0;

#pragma unroll
    for (int p = 0; p < 4; p++) {
        int n = n0 + p;
        float dd0 = av[p][0] - 1.0f, dd1 = av[p][1] - 1.0f,
              dd2 = av[p][2] - 1.0f, dd3 = av[p][3] - 1.0f;
        unsigned v0 = (lane < 30) ? ord32(dd0) : 0u;
        unsigned v1 = (lane < 30) ? ord32(dd1) : 0u;
        unsigned v2 = (lane < 30) ? ord32(dd2) : 0u;
        unsigned v3 = (lane < 30) ? ord32(dd3) : 0u;

        // binary search for the 30th-largest value T (exact)
        unsigned T = 0u;
#pragma unroll
        for (int bit = 31; bit >= 0; bit--) {
            unsigned cand = T | (1u << bit);
            unsigned cm1 = cand - 1u;
            int c = 0;
            ICNT(c, v0, cm1); ICNT(c, v1, cm1);
            ICNT(c, v2, cm1); ICNT(c, v3, cm1);
            c = __reduce_add_sync(0xffffffffu, c);
            if (c >= KN) T = cand;
        }

        bool gt0 = v0 > T, gt1 = v1 > T, gt2 = v2 > T, gt3 = v3 > T;
        bool eq0 = v0 == T, eq1 = v1 == T, eq2 = v2 == T, eq3 = v3 == T;
        int G = __reduce_add_sync(0xffffffffu,
                                  (int)gt0 + (int)gt1 + (int)gt2 + (int)gt3);
        int Bq = KN - G;

        unsigned e0 = __ballot_sync(0xffffffffu, eq0);
        unsigned e1 = __ballot_sync(0xffffffffu, eq1);
        unsigned e2 = __ballot_sync(0xffffffffu, eq2);
        unsigned e3 = __ballot_sync(0xffffffffu, eq3);
        unsigned lt = (1u << lane) - 1u;
        int el0 = __popc(e0 & lt) + __popc(e1 & lt) + __popc(e2 & lt) + __popc(e3 & lt);
        int el1 = el0 + (int)eq0;
        int el2 = el1 + (int)eq1;
        int el3 = el2 + (int)eq2;
        bool sel0 = gt0 || (eq0 && el0 < Bq);
        bool sel1 = gt1 || (eq1 && el1 < Bq);
        bool sel2 = gt2 || (eq2 && el2 < Bq);
        bool sel3 = gt3 || (eq3 && el3 < Bq);

        unsigned s0 = __ballot_sync(0xffffffffu, sel0);
        unsigned s1 = __ballot_sync(0xffffffffu, sel1);
        unsigned s2 = __ballot_sync(0xffffffffu, sel2);
        unsigned s3 = __ballot_sync(0xffffffffu, sel3);
        int q0 = __popc(s0 & lt) + __popc(s1 & lt) + __popc(s2 & lt) + __popc(s3 & lt);
        int q1 = q0 + (int)sel0;
        int q2 = q1 + (int)sel1;
        int q3 = q2 + (int)sel2;
        int jb = 4 * lane;
        if (sel0) { selkW[q0] = ((unsigned long long)v0 << 32) | (unsigned)(KS-1-jb);
                    selvW[q0] = dd0; seljW[q0] = jb; }
        if (sel1) { selkW[q1] = ((unsigned long long)v1 << 32) | (unsigned)(KS-2-jb);
                    selvW[q1] = dd1; seljW[q1] = jb + 1; }
        if (sel2) { selkW[q2] = ((unsigned long long)v2 << 32) | (unsigned)(KS-3-jb);
                    selvW[q2] = dd2; seljW[q2] = jb + 2; }
        if (sel3) { selkW[q3] = ((unsigned long long)v3 << 32) | (unsigned)(KS-4-jb);
                    selvW[q3] = dd3; seljW[q3] = jb + 3; }
        __syncwarp();

        // rank the 30 survivors among themselves (u64 keys, all distinct)
        if (lane < 30) {
            unsigned long long mykey = selkW[lane];
            int rank = 0;
#pragma unroll 6
            for (int k = 0; k < KN; k++) rank += (int)(selkW[k] > mykey);
            td[rank] = selvW[lane];
            tj[rank] = seljW[lane];
        }
        __syncwarp();

        // kpam layer 1 + relu (stride-33 rows: conflict-free)
        float a1v = 0.f;
        {
            const float* wr = w1s + jl * WST;
            for (int k = 0; k < KN; k++) a1v = fmaf(td[k], wr[k], a1v);
            a1v = fmaxf(a1v, 0.f);
        }
        abw[lane] = a1v;
        __syncwarp();
        float pv = 0.f;
        {
            const float* wr = w2s + jl * WST;
            for (int o = 0; o < KN; o++) pv = fmaf(abw[o], wr[o], pv);
        }
        float pm = (lane < 30) ? pv : -1e30f;
        float mx = wmax(pm);
        float e = (lane < 30) ? __expf(pm - mx) : 0.f;
        float ssum = wsum(e);
        float attn = e / ssum;

        if (lane < 30) {
            size_t o = ((size_t)b * NP + n) * KN + lane;
            g_AJ[o] = make_float2(attn, __int_as_float(tj[lane]));
        }

        float px = pxv[p], py = pyv[p], pz = pzv[p];
        float qd0 = m0[0]*px*px + m0[3]*py*py + m0[5]*pz*pz +
                    2.f*(m0[1]*px*py + m0[2]*px*pz + m0[4]*py*pz);
        float qd1 = m1[0]*px*px + m1[3]*py*py + m1[5]*pz*pz +
                    2.f*(m1[1]*px*py + m1[2]*px*pz + m1[4]*py*pz);
        float s1g0 = 0.f, s2g0 = 0.f, s1g1 = 0.f, s2g1 = 0.f;
        if (lane < 30) {
            int j = tj[lane];
            float a = attn, a2 = attn * attn;
            s1g0 = a * (srow[j]       - (dg00*px + dg01*py + dg02*pz));
            s1g1 = a * (srow[120 + j] - (dg10*px + dg11*py + dg12*pz));
            const float* sd0 = sdv + j * 3;
            const float* sd1 = sdv + (120 + j) * 3;
            s2g0 = a2 * (ssv[j]       - 2.f*(sd0[0]*px + sd0[1]*py + sd0[2]*pz) + qd0);
            s2g1 = a2 * (ssv[120 + j] - 2.f*(sd1[0]*px + sd1[1]*py + sd1[2]*pz) + qd1);
        }
        s1g0 = wsum(s1g0); s2g0 = wsum(s2g0); s1g1 = wsum(s1g1); s2g1 = wsum(s2g1);
        if (lane == 0) { acc0 += s1g0; acc1 += s2g0; acc2 += s1g1; acc3 += s2g1; }
        __syncwarp();
    }

    if (lane == 0) {
        atomicAdd(&bacc[0], acc0); atomicAdd(&bacc[1], acc1);
        atomicAdd(&bacc[2], acc2); atomicAdd(&bacc[3], acc3);
    }
    __syncthreads();
    if (tid < 4) atomicAdd(&g_stats[b][tid >> 1][tid & 1], bacc[tid]);
}

// ----------------- K3 (combined attn+idx loads) ---------
#define P_S    0
#define P_MLP  61440
#define P_TAJ  64512
#define S3_TOTAL 79872
#define GRP 5
#define K3_WARPS_TOTAL 2368

__global__ void __launch_bounds__(512, 2)
k3_out(const float* __restrict__ points,
       const float* __restrict__ feature,
       const float* __restrict__ conv_w,
       const float* __restrict__ gamma,
       const float* __restrict__ beta,
       const float* __restrict__ mlp_w,
       const float* __restrict__ mlp_b,
       float* __restrict__ out)
{
    extern __shared__ unsigned char sm[];
    float* Ss = (float*)(sm + P_S);
    float* mw = (float*)(sm + P_MLP);
    float2* taj = (float2*)(sm + P_TAJ);
    __shared__ float s_ms[4];
    __shared__ float s_A[128];
    __shared__ float s_Bv[128];

    int tid = threadIdx.x, b = blockIdx.y;
    if (tid < 2) {
        double cnt = 64.0 * 30.0 * 8192.0;
        double mu = g_stats[b][tid][0] / cnt;
        double var = g_stats[b][tid][1] / cnt - mu * mu;
        s_ms[tid] = (float)mu;
        s_ms[2 + tid] = (float)(1.0 / sqrt(var + 1e-5));
    }
    __syncthreads();
    if (tid < 128) {
        int g = tid >> 6;
        float A = s_ms[2 + g] * __ldg(&gamma[tid]);
        s_A[tid] = A;
        s_Bv[tid] = __ldg(&beta[tid]) - s_ms[g] * A;
    }
    for (int i = tid; i < 768; i += 512) mw[i] = mlp_w[i];
    __syncthreads();
    {
        float4* dst = (float4*)Ss;
        const float4* srcp = (const float4*)&g_S[b][0];
        const float4* A4 = (const float4*)s_A;
        for (int i = tid; i < 3840; i += 512) {
            float4 v = srcp[i];
            float4 a = A4[i & 31];
            v.x *= a.x; v.y *= a.y; v.z *= a.z; v.w *= a.w;
            dst[i] = v;
        }
    }
    __syncthreads();

    int w = tid >> 5, lane = tid & 31;
    int gw = blockIdx.x * 16 + w;

    uint32_t taj_u = (uint32_t)__cvta_generic_to_shared(taj);
#pragma unroll
    for (int t4 = 0; t4 < 4; t4++) {
        int n = gw + t4 * K3_WARPS_TOTAL;
        if (n < NP && lane < 30) {
            size_t o = ((size_t)b * NP + n) * KN + lane;
            uint32_t off = ((w * 4 + t4) * KN + lane) * 8;
            cpa8(taj_u + off, (const void*)(g_AJ + o));
        }
        cpa_commit();
    }

    float A[4], Bv[4], nAD[4][3], wo[3][4], wf[3][4];
#pragma unroll
    for (int q = 0; q < 4; q++) {
        int o = 4 * lane + q;
        A[q] = s_A[o];
        Bv[q] = s_Bv[o];
        nAD[q][0] = -A[q] * __ldg(&conv_w[o * 131 + 128]);
        nAD[q][1] = -A[q] * __ldg(&conv_w[o * 131 + 129]);
        nAD[q][2] = -A[q] * __ldg(&conv_w[o * 131 + 130]);
#pragma unroll
        for (int t = 0; t < 3; t++) {
            wo[t][q] = mw[t * 256 + o];
            wf[t][q] = mw[t * 256 + 128 + o];
        }
    }
    float b0 = __ldg(&mlp_b[0]), b1 = __ldg(&mlp_b[1]), b2 = __ldg(&mlp_b[2]);
    const float4* S4 = (const float4*)Ss;
    const float4* f4 = (const float4*)feature;

#pragma unroll
    for (int t4 = 0; t4 < 4; t4++) {
        int n = gw + t4 * K3_WARPS_TOTAL;
        if (n >= NP) break;
        if (t4 == 0) cpa_wait<3>();
        else if (t4 == 1) cpa_wait<2>();
        else if (t4 == 2) cpa_wait<1>();
        else cpa_wait<0>();
        __syncwarp();

        const float2* tajw = taj + (w * 4 + t4) * KN;

        float px = __ldg(&points[((size_t)b * NP + n) * 3 + 0]);
        float py = __ldg(&points[((size_t)b * NP + n) * 3 + 1]);
        float pz = __ldg(&points[((size_t)b * NP + n) * 3 + 2]);
        float4 fv = f4[((size_t)b * NP + n) * 32 + lane];

        float edp[4];
#pragma unroll
        for (int q = 0; q < 4; q++) edp[q] = nAD[q][0]*px + nAD[q][1]*py + nAD[q][2]*pz;

        float mxv[4];
#pragma unroll
        for (int q = 0; q < 4; q++) mxv[q] = -1e30f;

#pragma unroll
        for (int g5 = 0; g5 < KN / GRP; g5++) {
            float a5[GRP]; int j5[GRP]; float4 s5[GRP];
#pragma unroll
            for (int t = 0; t < GRP; t++) {
                float2 aj = tajw[g5 * GRP + t];
                a5[t] = aj.x;
                j5[t] = __float_as_int(aj.y);
            }
#pragma unroll
            for (int t = 0; t < GRP; t++) s5[t] = S4[j5[t] * 32 + lane];
#pragma unroll
            for (int t = 0; t < GRP; t++) {
                float a = a5[t];
                float v0 = fmaf(a, s5[t].x, a * edp[0]); mxv[0] = fmaxf(mxv[0], v0);
                float v1 = fmaf(a, s5[t].y, a * edp[1]); mxv[1] = fmaxf(mxv[1], v1);
                float v2 = fmaf(a, s5[t].z, a * edp[2]); mxv[2] = fmaxf(mxv[2], v2);
                float v3 = fmaf(a, s5[t].w, a * edp[3]); mxv[3] = fmaxf(mxv[3], v3);
            }
        }

        float o0 = 0.f, o1 = 0.f, o2 = 0.f;
        float fr[4] = { fv.x, fv.y, fv.z, fv.w };
#pragma unroll
        for (int q = 0; q < 4; q++) {
            float z = mxv[q] + Bv[q];
            float ym = (z >= 0.f) ? z : 0.2f * z;
            o0 = fmaf(wo[0][q], ym, fmaf(wf[0][q], fr[q], o0));
            o1 = fmaf(wo[1][q], ym, fmaf(wf[1][q], fr[q], o1));
            o2 = fmaf(wo[2][q], ym, fmaf(wf[2][q], fr[q], o2));
        }
        o0 = wsum(o0); o1 = wsum(o1); o2 = wsum(o2);
        if (lane == 0) {
            out[((size_t)b * 3 + 0) * NP + n] = o0 + b0;
            out[((size_t)b * 3 + 1) * NP + n] = o1 + b1;
            out[((size_t)b * 3 + 2) * NP + n] = o2 + b2;
        }
    }
}

// ----------------- host: numpy RandomState(1234) key indices -----------------
static void compute_key_indices(int* outv) {
    static const int NMT = 624;
    unsigned mt[624]; int mti;
    mt[0] = 1234u;
    for (int i = 1; i < NMT; i++)
        mt[i] = 1812433253u * (mt[i-1] ^ (mt[i-1] >> 30)) + (unsigned)i;
    mti = NMT;
    auto nxt = [&]() -> unsigned {
        if (mti >= NMT) {
            for (int k = 0; k < NMT; k++) {
                unsigned y = (mt[k] & 0x80000000u) | (mt[(k+1) % NMT] & 0x7fffffffu);
                mt[k] = mt[(k+397) % NMT] ^ (y >> 1) ^ ((y & 1u) ? 2567483615u : 0u);
            }
            mti = 0;
        }
        unsigned y = mt[mti++];
        y ^= y >> 11; y ^= (y << 7) & 2636928640u; y ^= (y << 15) & 4022730752u; y ^= y >> 18;
        return y;
    };
    auto interval = [&](unsigned mx) -> unsigned {
        unsigned mask = mx;
        mask |= mask >> 1; mask |= mask >> 2; mask |= mask >> 4;
        mask |= mask >> 8; mask |= mask >> 16;
        unsigned v;
        while ((v = nxt() & mask) > mx) {}
        return v;
    };
    static int arr[NP];
    for (int i = 0; i < NP; i++) arr[i] = i;
    for (int i = NP - 1; i > 0; i--) {
        unsigned j = interval((unsigned)i);
        int t = arr[i]; arr[i] = arr[j]; arr[j] = t;
    }
    for (int i = 0; i < KS; i++) outv[i] = arr[i];
}

extern "C" void kernel_launch(void* const* d_in, const int* in_sizes, int n_in,
                              void* d_out, int out_size) {
    const float* points  = (const float*)d_in[0];
    const float* feature = (const float*)d_in[1];
    const float* inst    = (const float*)d_in[2];
    const float* w1      = (const float*)d_in[3];
    const float* w2      = (const float*)d_in[4];
    const float* conv_w  = (const float*)d_in[5];
    const float* gamma   = (const float*)d_in[6];
    const float* beta    = (const float*)d_in[7];
    const float* mlp_w   = (const float*)d_in[8];
    const float* mlp_b   = (const float*)d_in[9];
    float* out = (float*)d_out;

    KIdx kid;
    compute_key_indices(kid.v);

    cudaFuncSetAttribute(k1_attn, cudaFuncAttributeMaxDynamicSharedMemorySize, S1_TOTAL);
    cudaFuncSetAttribute(k3_out,  cudaFuncAttributeMaxDynamicSharedMemorySize, S3_TOTAL);

    k_tr<<<dim3(5, 5), dim3(32, 32)>>>(conv_w);
    k0_prep<<<dim3(KS, NB), 128>>>(points, feature, inst, kid);
    k1_attn<<<dim3(512, NB), 128, S1_TOTAL>>>(points, inst, w1, w2);
    k3_out<<<dim3(148, NB), 512, S3_TOTAL>>>(points, feature, conv_w, gamma, beta,
                                             mlp_w, mlp_b, out);
}